// round 4
// baseline (speedup 1.0000x reference)
#include <cuda_runtime.h>
#include <cuda_fp16.h>
#include <mma.h>
#include <cstdint>

using namespace nvcuda;

// Problem shape (fixed by the reference)
constexpr int M = 4096;     // B*S
constexpr int N = 16384;    // out_features
constexpr int K = 4096;     // in_features

// CTA tile
constexpr int BM = 128;
constexpr int BN = 128;
constexpr int BK = 64;
constexpr int KT = K / BK;

constexpr int APAD = 8;
constexpr int BPAD = 8;

// ---------------------------------------------------------------------------
// Weight dtype detection: harness may deliver the int8 weight as int8 or as
// sign-extended int32. int32 little-endian groups have bytes[1..3] == 0x00 or
// 0xFF (sign extension, all equal); random int8 data matches this across 16
// groups with probability ~(1.2e-7)^16 ~ 0. Deterministic for fixed inputs.
// ---------------------------------------------------------------------------
__device__ int g_w32;

__global__ void detect_w_kernel(const unsigned char* __restrict__ w) {
    int all = 1;
    #pragma unroll
    for (int i = 0; i < 16; i++) {
        unsigned char b1 = w[4 * i + 1], b2 = w[4 * i + 2], b3 = w[4 * i + 3];
        int sext = (int)(((b1 == 0u) || (b1 == 0xFFu)) && (b2 == b1) && (b3 == b1));
        all &= sext;
    }
    g_w32 = all;
}

// Extract uint4 component by (unrolled-constant) index without taking the
// address of a register variable (which would force a local-memory spill).
__device__ __forceinline__ unsigned int u4_lane(const uint4& v, int j) {
    switch (j) {
        case 0: return v.x;
        case 1: return v.y;
        case 2: return v.z;
        default: return v.w;
    }
}

template <int W32>
__global__ __launch_bounds__(256, 1)
void w8a16_gemm_kernel(const float* __restrict__ X,      // [M, K] fp32 (fp16 values)
                       const void*  __restrict__ Wraw,   // [K, N] int8 or int32
                       const float* __restrict__ Wscale, // [N]
                       const float* __restrict__ Woff,   // [N]
                       const float* __restrict__ Bias,   // [N]
                       float*       __restrict__ Out)    // [M, N] fp32
{
    if (g_w32 != W32) return;  // wrong instantiation for the actual dtype

    __shared__ __align__(16) __half As[BM][BK + APAD];   // 18,432 B
    __shared__ __align__(16) __half Bs[BK][BN + BPAD];   // 17,408 B
    __shared__ float stage[8][256];                      //  8,192 B
    __shared__ float s_sc[BN];
    __shared__ float s_of[BN];

    const int tid    = threadIdx.x;
    const int lane   = tid & 31;
    const int wid    = tid >> 5;       // 0..7
    const int warp_m = wid & 3;        // 32-row slab
    const int warp_n = wid >> 2;       // 64-col slab

    const int bm = blockIdx.y * BM;
    const int bn = blockIdx.x * BN;

    const int8_t* W8  = (const int8_t*)Wraw;
    const int*    W32p = (const int*)Wraw;

    if (tid < BN) {
        s_sc[tid] = Wscale[bn + tid];
        s_of[tid] = Woff[bn + tid];
    }

    // A loader: 128 rows x 64 fp32; float4 per ld; 16 threads/row, 8 passes
    const int arow = tid >> 4;             // 0..15
    const int acol = (tid & 15) * 4;       // 0..60
    // B loader: 64 rows x 128 cols; each thread covers 16 cols, 2 row passes
    const int brow = tid >> 3;             // 0..31
    const int bcol = (tid & 7) * 16;       // 0..112

    float4 aR[8];
    uint4  bR[W32 ? 8 : 2];

    auto loadG = [&](int kt) {
        const int k0 = kt * BK;
        #pragma unroll
        for (int p = 0; p < 8; p++)
            aR[p] = *reinterpret_cast<const float4*>(
                X + (size_t)(bm + arow + p * 16) * K + k0 + acol);
        if (W32) {
            #pragma unroll
            for (int p = 0; p < 2; p++)
                #pragma unroll
                for (int q = 0; q < 4; q++)
                    bR[p * 4 + q] = *reinterpret_cast<const uint4*>(
                        W32p + (size_t)(k0 + brow + p * 32) * N + bn + bcol + q * 4);
        } else {
            #pragma unroll
            for (int p = 0; p < 2; p++)
                bR[p] = *reinterpret_cast<const uint4*>(
                    W8 + (size_t)(k0 + brow + p * 32) * N + bn + bcol);
        }
    };

    auto storeS = [&]() {
        #pragma unroll
        for (int p = 0; p < 8; p++) {
            __half2 h01 = __floats2half2_rn(aR[p].x, aR[p].y);
            __half2 h23 = __floats2half2_rn(aR[p].z, aR[p].w);
            __half2* dst = reinterpret_cast<__half2*>(&As[arow + p * 16][acol]);
            dst[0] = h01;
            dst[1] = h23;
        }
        #pragma unroll
        for (int p = 0; p < 2; p++) {
            __align__(16) __half hb[16];
            #pragma unroll
            for (int c = 0; c < 16; c++) {
                int q;
                if (W32) {
                    q = (int)u4_lane(bR[p * 4 + (c >> 2)], c & 3);
                } else {
                    unsigned int word = u4_lane(bR[p], c >> 2);
                    q = (int)(int8_t)((word >> ((c & 3) * 8)) & 0xFF);
                }
                // fp16((q + off) * sc): q+off exact in fp32, product exact in
                // fp32, one rounding -> bit-identical to the fp16 reference.
                hb[c] = __float2half_rn(((float)q + s_of[bcol + c]) * s_sc[bcol + c]);
            }
            *reinterpret_cast<uint4*>(&Bs[brow + p * 32][bcol]) =
                *reinterpret_cast<const uint4*>(&hb[0]);
            *reinterpret_cast<uint4*>(&Bs[brow + p * 32][bcol + 8]) =
                *reinterpret_cast<const uint4*>(&hb[8]);
        }
    };

    wmma::fragment<wmma::accumulator, 16, 16, 16, float> acc[2][4];
    #pragma unroll
    for (int i = 0; i < 2; i++)
        #pragma unroll
        for (int j = 0; j < 4; j++)
            wmma::fill_fragment(acc[i][j], 0.0f);

    loadG(0);
    __syncthreads();   // s_sc/s_of visible before dequant
    storeS();
    __syncthreads();

    for (int kt = 0; kt < KT; kt++) {
        if (kt + 1 < KT) loadG(kt + 1);   // prefetch next tile into registers

        #pragma unroll
        for (int kk = 0; kk < BK; kk += 16) {
            wmma::fragment<wmma::matrix_a, 16, 16, 16, __half, wmma::row_major> af[2];
            wmma::fragment<wmma::matrix_b, 16, 16, 16, __half, wmma::row_major> bf[4];
            #pragma unroll
            for (int i = 0; i < 2; i++)
                wmma::load_matrix_sync(af[i], &As[warp_m * 32 + i * 16][kk], BK + APAD);
            #pragma unroll
            for (int j = 0; j < 4; j++)
                wmma::load_matrix_sync(bf[j], &Bs[kk][warp_n * 64 + j * 16], BN + BPAD);
            #pragma unroll
            for (int i = 0; i < 2; i++)
                #pragma unroll
                for (int j = 0; j < 4; j++)
                    wmma::mma_sync(acc[i][j], af[i], bf[j], acc[i][j]);
        }

        __syncthreads();
        if (kt + 1 < KT) {
            storeS();
            __syncthreads();
        }
    }

    // Epilogue. Emulate the reference exactly: r = fp16(acc); y = fp16(r + b);
    // store upcast to fp32.
    #pragma unroll
    for (int i = 0; i < 2; i++) {
        #pragma unroll
        for (int j = 0; j < 4; j++) {
            wmma::store_matrix_sync(&stage[wid][0], acc[i][j], 16, wmma::mem_row_major);
            __syncwarp();
            const int r   = lane >> 1;          // 0..15
            const int c0  = (lane & 1) * 8;     // 0 or 8
            const int gm  = bm + warp_m * 32 + i * 16 + r;
            const int gnb = bn + warp_n * 64 + j * 16 + c0;
            float o[8];
            #pragma unroll
            for (int c = 0; c < 8; c++) {
                __half h = __float2half_rn(stage[wid][r * 16 + c0 + c]);
                __half b = __float2half_rn(Bias[gnb + c]);
                o[c] = __half2float(__hadd(h, b));
            }
            *reinterpret_cast<float4*>(Out + (size_t)gm * N + gnb) =
                make_float4(o[0], o[1], o[2], o[3]);
            *reinterpret_cast<float4*>(Out + (size_t)gm * N + gnb + 4) =
                make_float4(o[4], o[5], o[6], o[7]);
            __syncwarp();
        }
    }
}

extern "C" void kernel_launch(void* const* d_in, const int* in_sizes, int n_in,
                              void* d_out, int out_size)
{
    // metadata order: x, weight, weight_scale, weight_offset, bias
    const float* X      = (const float*)d_in[0];
    const void*  W      = d_in[1];
    const float* Wscale = (const float*)d_in[2];
    const float* Woff   = (const float*)d_in[3];
    const float* Bias   = (const float*)d_in[4];
    float*       Out    = (float*)d_out;

    detect_w_kernel<<<1, 1>>>((const unsigned char*)W);

    dim3 grid(N / BN, M / BM);   // (128, 32): n-major wave shares the A stripe
    dim3 block(256);
    // Launch both dtype variants; the mismatched one exits immediately.
    w8a16_gemm_kernel<0><<<grid, block>>>(X, W, Wscale, Woff, Bias, Out);
    w8a16_gemm_kernel<1><<<grid, block>>>(X, W, Wscale, Woff, Bias, Out);
}

// round 6
// speedup vs baseline: 2.7173x; 2.7173x over previous
#include <cuda_runtime.h>
#include <cuda_fp16.h>
#include <cstdint>

// ---------------------------------------------------------------------------
// Problem shape (fixed by the reference)
// ---------------------------------------------------------------------------
constexpr int M = 4096;      // B*S
constexpr int N = 16384;     // out_features
constexpr int K = 4096;      // in_features

// GEMM tiling
constexpr int BM = 128;
constexpr int BN = 256;
constexpr int BK = 64;                      // halves per k-tile = 128 B/row
constexpr int KT = K / BK;                  // 64 k-iterations
constexpr int STAGES = 4;

constexpr int A_BYTES = BM * 128;           // 16 KB
constexpr int B_BYTES = BN * 128;           // 32 KB
constexpr int STAGE_BYTES = A_BYTES + B_BYTES;        // 48 KB
constexpr int SMEM_TOTAL  = STAGES * STAGE_BYTES;     // 192 KB

// Scratch operand buffers (device globals: the sanctioned no-alloc scratch)
__device__ __align__(1024) __half g_XH[(size_t)M * K];   // fp16 X,   [M][K]
__device__ __align__(1024) __half g_WH[(size_t)N * K];   // deq W^T,  [N][K]
__device__ int g_w32;

// ---------------------------------------------------------------------------
// Pre-kernels
// ---------------------------------------------------------------------------
// Weight dtype detection (int8 vs sign-extended int32 delivery). Verified R4.
__global__ void detect_w_kernel(const unsigned char* __restrict__ w) {
    int all = 1;
    #pragma unroll
    for (int i = 0; i < 16; i++) {
        unsigned char b1 = w[4 * i + 1], b2 = w[4 * i + 2], b3 = w[4 * i + 3];
        int sext = (int)(((b1 == 0u) || (b1 == 0xFFu)) && (b2 == b1) && (b3 == b1));
        all &= sext;
    }
    g_w32 = all;
}

// X fp32 (holding exact fp16 values) -> fp16. Lossless.
__global__ void convert_x_kernel(const float4* __restrict__ X) {
    size_t i = (size_t)blockIdx.x * blockDim.x + threadIdx.x;   // < M*K/4
    float4 v = X[i];
    __half2* dst = reinterpret_cast<__half2*>(g_XH);
    dst[2 * i]     = __floats2half2_rn(v.x, v.y);
    dst[2 * i + 1] = __floats2half2_rn(v.z, v.w);
}

// Dequantize + transpose: WH[n][k] = fp16((W[k][n] + off[n]) * sc[n]).
// q+off exact in fp32, product exact in fp32, single fp16 rounding ->
// bit-identical to the reference's all-fp16 dequant (R4 passed at 5.6e-5).
template <int W32>
__global__ void dequant_w_kernel(const void* __restrict__ Wraw,
                                 const float* __restrict__ sc,
                                 const float* __restrict__ off) {
    if (g_w32 != W32) return;
    __shared__ __half tile[32][33];
    const int n0 = blockIdx.x * 32, k0 = blockIdx.y * 32;
    const int tx = threadIdx.x, ty = threadIdx.y;            // (32, 8)
    const float s = sc[n0 + tx], o = off[n0 + tx];
    #pragma unroll
    for (int j = 0; j < 4; j++) {
        const int k = k0 + ty + j * 8;
        int q;
        if (W32) q = ((const int*)Wraw)[(size_t)k * N + n0 + tx];
        else     q = (int)((const int8_t*)Wraw)[(size_t)k * N + n0 + tx];
        tile[ty + j * 8][tx] = __float2half_rn(((float)q + o) * s);
    }
    __syncthreads();
    #pragma unroll
    for (int j = 0; j < 4; j++) {
        const int n = n0 + ty + j * 8;
        g_WH[(size_t)n * K + k0 + tx] = tile[tx][ty + j * 8];
    }
}

// ---------------------------------------------------------------------------
// MMA helpers (baseline compute_103 PTX: ldmatrix + mma.sync HMMA)
// ---------------------------------------------------------------------------
__device__ __forceinline__ void ldsm4(uint32_t* r, uint32_t addr) {
    asm volatile("ldmatrix.sync.aligned.m8n8.x4.shared.b16 {%0,%1,%2,%3}, [%4];"
                 : "=r"(r[0]), "=r"(r[1]), "=r"(r[2]), "=r"(r[3]) : "r"(addr));
}
__device__ __forceinline__ void mma16816(float* c, const uint32_t* a,
                                         const uint32_t* b) {
    asm volatile(
        "mma.sync.aligned.m16n8k16.row.col.f32.f16.f16.f32 "
        "{%0,%1,%2,%3}, {%4,%5,%6,%7}, {%8,%9}, {%0,%1,%2,%3};"
        : "+f"(c[0]), "+f"(c[1]), "+f"(c[2]), "+f"(c[3])
        : "r"(a[0]), "r"(a[1]), "r"(a[2]), "r"(a[3]), "r"(b[0]), "r"(b[1]));
}

// ---------------------------------------------------------------------------
// GEMM: Out[BM x BN per CTA] = XH @ WH^T + bias, 4-stage cp.async pipeline
// ---------------------------------------------------------------------------
__global__ __launch_bounds__(256, 1)
void gemm_kernel(const float* __restrict__ Bias, float* __restrict__ Out)
{
    extern __shared__ __align__(1024) char smem[];
    const uint32_t sb = (uint32_t)__cvta_generic_to_shared(smem);
    const int tid  = threadIdx.x, lane = tid & 31, wid = tid >> 5;
    const int wm   = wid & 1;              // 2 m-slabs of 64 rows
    const int wn   = wid >> 1;             // 4 n-slabs of 64 cols
    const int bm   = blockIdx.x * BM;      // grid.x = 32 (m fastest -> L2 reuse)
    const int bn   = blockIdx.y * BN;

    // cp.async mapping: warp covers 4 rows x 8 chunks (16B) per pass
    const int lrow   = tid >> 3;           // 0..31
    const int lchunk = tid & 7;            // 0..7
    const __half* gA = g_XH + (size_t)(bm + lrow) * K + lchunk * 8;
    const __half* gB = g_WH + (size_t)(bn + lrow) * K + lchunk * 8;
    const int lsw = lchunk ^ (lrow & 7);   // swizzled chunk (row&7 invariant mod 32)

    auto issue_stage = [&](int kt) {
        const int s = kt & (STAGES - 1);
        const uint32_t As = sb + s * STAGE_BYTES;
        const uint32_t Bs = As + A_BYTES;
        const int k0 = kt * BK;
        #pragma unroll
        for (int p = 0; p < 4; p++) {
            const uint32_t dst = As + (lrow + p * 32) * 128 + (lsw << 4);
            asm volatile("cp.async.cg.shared.global [%0], [%1], 16;"
                         :: "r"(dst), "l"(gA + (size_t)p * 32 * K + k0) : "memory");
        }
        #pragma unroll
        for (int p = 0; p < 8; p++) {
            const uint32_t dst = Bs + (lrow + p * 32) * 128 + (lsw << 4);
            asm volatile("cp.async.cg.shared.global [%0], [%1], 16;"
                         :: "r"(dst), "l"(gB + (size_t)p * 32 * K + k0) : "memory");
        }
        asm volatile("cp.async.commit_group;" ::: "memory");
    };

    // ldmatrix per-lane addressing constants
    const int g    = lane >> 3, lr7 = lane & 7;
    const int arow = wm * 64 + (g & 1) * 8 + lr7;   // + i*16
    const int acs  = g >> 1;                        // A chunk selector (0/1)
    const int brow = wn * 64 + (g >> 1) * 8 + lr7;  // + j*16
    const int bcs  = g & 1;                         // B chunk selector (0/1)
    const int arow7 = arow & 7, brow7 = brow & 7;

    float acc[4][8][4];
    #pragma unroll
    for (int i = 0; i < 4; i++)
        #pragma unroll
        for (int j = 0; j < 8; j++)
            #pragma unroll
            for (int c = 0; c < 4; c++)
                acc[i][j][c] = 0.0f;

    #pragma unroll
    for (int s = 0; s < STAGES - 1; s++) issue_stage(s);

    for (int kt = 0; kt < KT; kt++) {
        asm volatile("cp.async.wait_group %0;" :: "n"(STAGES - 2));
        __syncthreads();
        const int s = kt & (STAGES - 1);
        const uint32_t As = sb + s * STAGE_BYTES;
        const uint32_t Bs = As + A_BYTES;

        #pragma unroll
        for (int kk = 0; kk < 4; kk++) {          // 4 x k16 per k-tile
            const int ck = kk * 2;                // chunk base (8 halves/chunk)
            uint32_t af[4][4], bf[4][4];
            #pragma unroll
            for (int i = 0; i < 4; i++)
                ldsm4(af[i], As + (arow + i * 16) * 128 +
                             (((ck + acs) ^ arow7) << 4));
            #pragma unroll
            for (int j = 0; j < 4; j++)
                ldsm4(bf[j], Bs + (brow + j * 16) * 128 +
                             (((ck + bcs) ^ brow7) << 4));
            #pragma unroll
            for (int i = 0; i < 4; i++)
                #pragma unroll
                for (int jj = 0; jj < 8; jj++)
                    mma16816(acc[i][jj], af[i], &bf[jj >> 1][(jj & 1) * 2]);
        }

        __syncthreads();
        if (kt + STAGES - 1 < KT) issue_stage(kt + STAGES - 1);
    }

    // Epilogue. Reference numerics: y = fp32( fp16(acc) + fp16(bias) ).
    const int r0  = lane >> 2;
    const int cof = (lane & 3) * 2;
    #pragma unroll
    for (int i = 0; i < 4; i++) {
        const int mrow = bm + wm * 64 + i * 16 + r0;
        #pragma unroll
        for (int jj = 0; jj < 8; jj++) {
            const int col = bn + wn * 64 + jj * 8 + cof;
            const __half b0 = __float2half_rn(__ldg(Bias + col));
            const __half b1 = __float2half_rn(__ldg(Bias + col + 1));
            float2 v0, v1;
            v0.x = __half2float(__hadd(__float2half_rn(acc[i][jj][0]), b0));
            v0.y = __half2float(__hadd(__float2half_rn(acc[i][jj][1]), b1));
            v1.x = __half2float(__hadd(__float2half_rn(acc[i][jj][2]), b0));
            v1.y = __half2float(__hadd(__float2half_rn(acc[i][jj][3]), b1));
            *reinterpret_cast<float2*>(Out + (size_t)mrow * N + col)       = v0;
            *reinterpret_cast<float2*>(Out + (size_t)(mrow + 8) * N + col) = v1;
        }
    }
}

// ---------------------------------------------------------------------------
// Host
// ---------------------------------------------------------------------------
extern "C" void kernel_launch(void* const* d_in, const int* in_sizes, int n_in,
                              void* d_out, int out_size)
{
    // metadata order: x, weight, weight_scale, weight_offset, bias
    const float* X    = (const float*)d_in[0];
    const void*  W    = d_in[1];
    const float* Wsc  = (const float*)d_in[2];
    const float* Woff = (const float*)d_in[3];
    const float* Bias = (const float*)d_in[4];
    float*       Out  = (float*)d_out;

    detect_w_kernel<<<1, 1>>>((const unsigned char*)W);
    convert_x_kernel<<<(int)((size_t)M * K / 4 / 256), 256>>>((const float4*)X);
    dim3 tb(32, 8);
    dequant_w_kernel<0><<<dim3(N / 32, K / 32), tb>>>(W, Wsc, Woff);
    dequant_w_kernel<1><<<dim3(N / 32, K / 32), tb>>>(W, Wsc, Woff);

    cudaFuncSetAttribute(gemm_kernel,
                         cudaFuncAttributeMaxDynamicSharedMemorySize, SMEM_TOTAL);
    gemm_kernel<<<dim3(M / BM, N / BN), 256, SMEM_TOTAL>>>(Bias, Out);
}